// round 16
// baseline (speedup 1.0000x reference)
#include <cuda_runtime.h>
#include <cuda_fp16.h>
#include <math.h>
#include <cstdint>

// ---------------------------------------------------------------------------
// Problem constants
// ---------------------------------------------------------------------------
namespace {
constexpr int cB  = 2;
constexpr int cS  = 2048;
constexpr int cH  = 4096;
constexpr int cNH = 32;
constexpr int cHD = 128;
constexpr int cM  = cB * cS;      // 4096
constexpr int cQKVN = 3 * cH;     // 12288

// GEMM tiling: 128x128 CTA tile, K-chunk 64, 2-stage cp.async ring
constexpr int GBM = 128, GBK = 64;
constexpr int SKB   = 144;                // 64 fp16 = 128B + 16 pad
constexpr int TILEB = GBM * SKB;          // 18432
constexpr int STAGE2 = 2 * TILEB;         // A,B = 36864
constexpr int SMEM_1T = 2 * STAGE2;       // 73728 (2-stage)
constexpr int MTILES = cM / GBM;          // 32
constexpr int GROUPM = 8;                 // supertile height (M-tiles)

// Attention: q-tile 64 rows, k-tile 64 rows, double-buffered, 2 tiles/stage
constexpr int ABQ = 64, ABK = 64;
constexpr int ROWB = 272;                 // 128 fp16 + pad
constexpr int ATILE = ABK * ROWB;         // 17408
constexpr int ASTAGE = 2 * ATILE;         // KH,VH = 34816
constexpr int AOFF_ALI = 2 * ASTAGE;      // 69632
constexpr int ATTN_SMEM = AOFF_ALI + 512; // 70144
}

// ---------------------------------------------------------------------------
// Scratch (__device__ globals)
// ---------------------------------------------------------------------------
__device__ __half g_qh[(size_t)cB * cNH * cS * cHD];
__device__ __half g_kh[(size_t)cB * cNH * cS * cHD];
__device__ __half g_vh[(size_t)cB * cNH * cS * cHD];

__device__ __half g_hid_hi[(size_t)cM * cH];
__device__ __half g_wqkv_hi[(size_t)cQKVN * cH];
__device__ __half g_wd_hi[(size_t)cH * cH];
__device__ __half g_ctx_hi[(size_t)cM * cH];

// ---------------------------------------------------------------------------
// PTX helpers — non-arch-specific only (mma.sync / ldmatrix / cp.async)
// ---------------------------------------------------------------------------
__device__ __forceinline__ uint32_t smem_u32(const void* p) {
    uint32_t a;
    asm("{ .reg .u64 t; cvta.to.shared.u64 t, %1; cvt.u32.u64 %0, t; }" : "=r"(a) : "l"(p));
    return a;
}
__device__ __forceinline__ void mma_f16(float* c, const uint32_t* a, const uint32_t* b) {
    asm volatile(
        "mma.sync.aligned.m16n8k16.row.col.f32.f16.f16.f32 "
        "{%0,%1,%2,%3}, {%4,%5,%6,%7}, {%8,%9}, {%0,%1,%2,%3};"
        : "+f"(c[0]), "+f"(c[1]), "+f"(c[2]), "+f"(c[3])
        : "r"(a[0]), "r"(a[1]), "r"(a[2]), "r"(a[3]), "r"(b[0]), "r"(b[1]));
}
__device__ __forceinline__ void ldsm_x4(uint32_t* r, uint32_t addr) {
    asm volatile("ldmatrix.sync.aligned.m8n8.x4.shared.b16 {%0,%1,%2,%3}, [%4];"
                 : "=r"(r[0]), "=r"(r[1]), "=r"(r[2]), "=r"(r[3]) : "r"(addr));
}
__device__ __forceinline__ void ldsm_x4_t(uint32_t* r, uint32_t addr) {
    asm volatile("ldmatrix.sync.aligned.m8n8.x4.trans.shared.b16 {%0,%1,%2,%3}, [%4];"
                 : "=r"(r[0]), "=r"(r[1]), "=r"(r[2]), "=r"(r[3]) : "r"(addr));
}
__device__ __forceinline__ void cp_async16(uint32_t s, const void* g) {
    asm volatile("cp.async.cg.shared.global [%0], [%1], 16;" :: "r"(s), "l"(g));
}
#define CP_COMMIT() asm volatile("cp.async.commit_group;" ::: "memory")
#define CP_WAIT(n)  asm volatile("cp.async.wait_group %0;" :: "n"(n) : "memory")

__device__ __forceinline__ uint32_t pack_f16(float lo, float hi) {
    uint32_t r;
    asm("cvt.rn.f16x2.f32 %0, %1, %2;" : "=r"(r) : "f"(hi), "f"(lo));
    return r;
}
// exp on the FMA pipe: valid for x <= 0; flushes below -87.
__device__ __forceinline__ float fast_exp(float x) {
    x = fmaxf(x, -87.0f);
    const float L2E = 1.4426950408889634f;
    float t = fmaf(x, L2E, 12582912.0f);
    float i = t - 12582912.0f;
    float f = fmaf(x, L2E, -i);
    float p =        1.3394582e-3f;
    p = fmaf(p, f, 9.6180217e-3f);
    p = fmaf(p, f, 5.5503368e-2f);
    p = fmaf(p, f, 2.4022652e-1f);
    p = fmaf(p, f, 6.9314718e-1f);
    p = fmaf(p, f, 1.0f);
    int e = (int)i;
    return __int_as_float((uint32_t)(e + 127) << 23) * p;
}

// ---------------------------------------------------------------------------
// fp32 -> fp16 (hi only)
// ---------------------------------------------------------------------------
__global__ __launch_bounds__(256) void split_fp32_hi(
    const float4* __restrict__ src, __half2* __restrict__ hi)
{
    const size_t i = (size_t)blockIdx.x * 256 + threadIdx.x;
    const float4 v = src[i];
    hi[2 * i]     = __halves2half2(__float2half_rn(v.x), __float2half_rn(v.y));
    hi[2 * i + 1] = __halves2half2(__float2half_rn(v.z), __float2half_rn(v.w));
}

// ---------------------------------------------------------------------------
// 1-term fp16 GEMM, K-chunk 64, 2-stage ring, L2 supertile swizzle (1-D grid).
// MODE 0: QKV -> scatter fp16 into g_qh/g_kh/g_vh (+bias); 3072 CTAs.
// MODE 1: dense -> out = acc + bias + residual (fp32); 1024 CTAs.
// ---------------------------------------------------------------------------
template <int MODE>
__global__ __launch_bounds__(256, 2) void tc_gemm_1t(
    const __half* __restrict__ Ahi, const __half* __restrict__ Bhi,
    const float* __restrict__ bias,
    const float* __restrict__ residual,
    float* __restrict__ out)
{
    extern __shared__ char smem[];
    const uint32_t sbase = smem_u32(smem);
    const int tid  = threadIdx.x;
    const int wid  = tid >> 5;
    const int lane = tid & 31;
    const int wm   = wid >> 2;
    const int wn   = wid & 3;

    // supertile swizzle: groups of GROUPM m-tiles; nx sweeps within a group
    constexpr int NXT = (MODE == 0) ? (cQKVN / 128) : (cH / 128);   // 96 / 32
    const int bid = blockIdx.x;
    const int grp = bid / (GROUPM * NXT);
    const int rem = bid % (GROUPM * NXT);
    const int my  = grp * GROUPM + (rem % GROUPM);
    const int nx  = rem / GROUPM;
    const int bm  = my * GBM;
    const int obase = nx * 128;

    const __half* Ah = Ahi + (size_t)bm * cH;
    const __half* Bh = Bhi + (size_t)obase * cH;

    float acc[4][4][4];
#pragma unroll
    for (int mi = 0; mi < 4; mi++)
#pragma unroll
        for (int nj = 0; nj < 4; nj++)
#pragma unroll
            for (int r = 0; r < 4; r++) acc[mi][nj][r] = 0.f;

    const int aRow = ((lane >> 3) & 1) * 8 + (lane & 7);
    const int aK   = (lane >> 4) * 8;
    const int bRow = ((lane >> 4) << 3) + (lane & 7);   // n-row within 16
    const int bK   = ((lane >> 3) & 1) * 8;

    auto load_chunk = [&](int stage, int k0) {
        const uint32_t sg = sbase + stage * STAGE2;
#pragma unroll
        for (int it = 0; it < 4; ++it) {
            const int c   = tid + it * 256;     // 0..1023
            const int row = c >> 3;
            const int kc  = c & 7;
            const uint32_t so = (uint32_t)(row * SKB + kc * 16);
            const size_t  go  = (size_t)row * cH + k0 + kc * 8;
            cp_async16(sg + 0 * TILEB + so, Ah + go);
            cp_async16(sg + 1 * TILEB + so, Bh + go);
        }
    };

    constexpr int NCH = cH / GBK;   // 64
    load_chunk(0, 0);
    CP_COMMIT();

    for (int ch = 0; ch < NCH; ++ch) {
        CP_WAIT(0);
        __syncthreads();   // current stage ready; prev compute done everywhere
        if (ch + 1 < NCH) {
            load_chunk((ch + 1) & 1, (ch + 1) * GBK);
            CP_COMMIT();
        }
        const uint32_t st = sbase + (ch & 1) * STAGE2;
#pragma unroll
        for (int ks = 0; ks < 4; ++ks) {
            uint32_t ah[4][4];
#pragma unroll
            for (int mi = 0; mi < 4; ++mi) {
                const uint32_t ao =
                    (uint32_t)((wm * 64 + mi * 16 + aRow) * SKB + (ks * 16 + aK) * 2);
                ldsm_x4(ah[mi], st + ao);
            }
#pragma unroll
            for (int nj2 = 0; nj2 < 2; ++nj2) {
                uint32_t bb[4];
                const uint32_t bo =
                    (uint32_t)((wn * 32 + nj2 * 16 + bRow) * SKB + (ks * 16 + bK) * 2);
                ldsm_x4(bb, st + TILEB + bo);
#pragma unroll
                for (int mi = 0; mi < 4; ++mi) {
                    mma_f16(acc[mi][2 * nj2],     ah[mi], bb);
                    mma_f16(acc[mi][2 * nj2 + 1], ah[mi], bb + 2);
                }
            }
        }
        __syncthreads();   // compute done before next iter overwrites stage
    }

    const int l4 = lane >> 2;
    const int l2 = (lane & 3) * 2;
#pragma unroll
    for (int mi = 0; mi < 4; ++mi) {
#pragma unroll
        for (int nj = 0; nj < 4; ++nj) {
            const int colT = wn * 32 + nj * 8 + l2;
            const int o    = obase + colT;
            const float2 bia = *(const float2*)&bias[o];
#pragma unroll
            for (int half = 0; half < 2; ++half) {
                const int m = bm + wm * 64 + mi * 16 + l4 + half * 8;
                const float vx = acc[mi][nj][half * 2 + 0] + bia.x;
                const float vy = acc[mi][nj][half * 2 + 1] + bia.y;
                if (MODE == 0) {
                    const int nh = nx / 3;
                    const int t  = nx % 3;
                    __half* dst = (t == 0) ? g_qh : (t == 1) ? g_kh : g_vh;
                    const int b = m / cS, s = m % cS;
                    const size_t idx =
                        ((size_t)(b * cNH + nh) * cS + s) * cHD + colT;
                    *(uint32_t*)&dst[idx] = pack_f16(vx, vy);
                } else {
                    const size_t idx = (size_t)m * cH + o;
                    const float2 res = *(const float2*)&residual[idx];
                    float2 v; v.x = vx + res.x; v.y = vy + res.y;
                    *(float2*)&out[idx] = v;
                }
            }
        }
    }
}

// ---------------------------------------------------------------------------
// Attention: 64 q-rows/CTA, 4 warps; 64-row K/V tiles double-buffered.
// QK and PV both 1-term fp16.
// ---------------------------------------------------------------------------
__global__ __launch_bounds__(128, 3) void attn_mma(const float* __restrict__ alibi)
{
    extern __shared__ char sm[];
    const uint32_t sb = smem_u32(sm);
    const int tid  = threadIdx.x;
    const int lane = tid & 31;
    const int w    = tid >> 5;
    const int qi   = (cS / ABQ - 1) - blockIdx.x;   // big tiles first
    const int bh   = blockIdx.y;
    const int b    = bh >> 5;
    const int nh   = bh & 31;
    const size_t hb = (size_t)bh * cS * cHD;
    const float inv_norm = 0.08838834764831845f;

    const int g    = lane >> 2;
    const int tig  = lane & 3;
    const int aRow = ((lane >> 3) & 1) * 8 + (lane & 7);
    const int aK   = (lane >> 4) * 8;
    const int bRow = ((lane >> 4) << 3) + (lane & 7);   // n-row within 16
    const int bK   = ((lane >> 3) & 1) * 8;
    const int vRow = (lane & 7) + (((lane >> 3) & 1) << 3);
    const int vSel = lane >> 4;

    // ---- stage Q (64 rows) into stage-0 KH area, ldsm into registers
#pragma unroll
    for (int i = 0; i < 8; i++) {
        const int id = tid + i * 128;
        const int r = id >> 4, c = id & 15;
        const size_t go = hb + (size_t)(qi * ABQ + r) * cHD + c * 8;
        cp_async16(sb + (uint32_t)(r * ROWB + c * 16), g_qh + go);
    }
    CP_COMMIT(); CP_WAIT(0);
    __syncthreads();

    uint32_t qh[8][4];
#pragma unroll
    for (int ks = 0; ks < 8; ks++) {
        const uint32_t ao = (uint32_t)((w * 16 + aRow) * ROWB + (ks * 16 + aK) * 2);
        ldsm_x4(qh[ks], sb + ao);
    }
    __syncthreads();

    float ctx[16][4];
#pragma unroll
    for (int t = 0; t < 16; t++)
#pragma unroll
        for (int r = 0; r < 4; r++) ctx[t][r] = 0.f;
    float m1 = -INFINITY, m2 = -INFINITY, l1 = 0.f, l2 = 0.f;
    const int row1 = qi * ABQ + w * 16 + g;
    const int row2 = row1 + 8;

    auto load_kv = [&](int stage, int kt) {
        const uint32_t stb = sb + stage * ASTAGE;
#pragma unroll
        for (int i = 0; i < 8; i++) {
            const int id = tid + i * 128;       // 0..1023
            const int r = id >> 4, c = id & 15;
            const size_t go = hb + (size_t)(kt * ABK + r) * cHD + c * 8;
            const uint32_t so = (uint32_t)(r * ROWB + c * 16);
            cp_async16(stb + 0 * ATILE + so, g_kh + go);
            cp_async16(stb + 1 * ATILE + so, g_vh + go);
        }
        if (tid < 64)
            ((float*)(sm + AOFF_ALI + stage * 256))[tid] =
                alibi[(size_t)bh * cS + kt * ABK + tid];
    };

    const int nkt = qi + 1;
    load_kv(0, 0);
    CP_COMMIT();

    for (int kt = 0; kt < nkt; kt++) {
        CP_WAIT(0);
        __syncthreads();
        if (kt + 1 < nkt) { load_kv((kt + 1) & 1, kt + 1); CP_COMMIT(); }
        const uint32_t stb = sb + (kt & 1) * ASTAGE;
        const float* als = (const float*)(sm + AOFF_ALI + (kt & 1) * 256);

        // ---- S = Q K^T over 64 columns (8 n8 tiles)
        float sacc[8][4];
#pragma unroll
        for (int j = 0; j < 8; j++)
#pragma unroll
            for (int r = 0; r < 4; r++) sacc[j][r] = 0.f;

#pragma unroll
        for (int nj2 = 0; nj2 < 4; ++nj2) {
#pragma unroll
            for (int ks = 0; ks < 8; ks++) {
                uint32_t kb[4];
                const uint32_t bo =
                    (uint32_t)((nj2 * 16 + bRow) * ROWB + (ks * 16 + bK) * 2);
                ldsm_x4(kb, stb + bo);
                mma_f16(sacc[2 * nj2],     qh[ks], kb);
                mma_f16(sacc[2 * nj2 + 1], qh[ks], kb + 2);
            }
        }

        // ---- scale + alibi + causal mask (only the diagonal tile can mask)
        const bool maskt = (kt == qi);
#pragma unroll
        for (int j = 0; j < 8; j++) {
            const int c0 = j * 8 + tig * 2;
            const float a0 = als[c0], a1 = als[c0 + 1];
            sacc[j][0] = fmaf(sacc[j][0], inv_norm, a0);
            sacc[j][1] = fmaf(sacc[j][1], inv_norm, a1);
            sacc[j][2] = fmaf(sacc[j][2], inv_norm, a0);
            sacc[j][3] = fmaf(sacc[j][3], inv_norm, a1);
            if (maskt) {
                const int cg = kt * ABK + c0;
                if (cg     > row1) sacc[j][0] = -100000.0f;
                if (cg + 1 > row1) sacc[j][1] = -100000.0f;
                if (cg     > row2) sacc[j][2] = -100000.0f;
                if (cg + 1 > row2) sacc[j][3] = -100000.0f;
            }
        }

        // ---- online softmax
        float mx1 = -INFINITY, mx2 = -INFINITY;
#pragma unroll
        for (int j = 0; j < 8; j++) {
            mx1 = fmaxf(mx1, fmaxf(sacc[j][0], sacc[j][1]));
            mx2 = fmaxf(mx2, fmaxf(sacc[j][2], sacc[j][3]));
        }
        mx1 = fmaxf(mx1, __shfl_xor_sync(0xffffffffu, mx1, 1));
        mx1 = fmaxf(mx1, __shfl_xor_sync(0xffffffffu, mx1, 2));
        mx2 = fmaxf(mx2, __shfl_xor_sync(0xffffffffu, mx2, 1));
        mx2 = fmaxf(mx2, __shfl_xor_sync(0xffffffffu, mx2, 2));

        const float mn1 = fmaxf(m1, mx1), mn2 = fmaxf(m2, mx2);
        const float sc1 = fast_exp(m1 - mn1), sc2 = fast_exp(m2 - mn2);
        float ls1 = 0.f, ls2 = 0.f;
#pragma unroll
        for (int j = 0; j < 8; j++) {
            sacc[j][0] = fast_exp(sacc[j][0] - mn1);
            sacc[j][1] = fast_exp(sacc[j][1] - mn1);
            sacc[j][2] = fast_exp(sacc[j][2] - mn2);
            sacc[j][3] = fast_exp(sacc[j][3] - mn2);
            ls1 += sacc[j][0] + sacc[j][1];
            ls2 += sacc[j][2] + sacc[j][3];
        }
        ls1 += __shfl_xor_sync(0xffffffffu, ls1, 1);
        ls1 += __shfl_xor_sync(0xffffffffu, ls1, 2);
        ls2 += __shfl_xor_sync(0xffffffffu, ls2, 1);
        ls2 += __shfl_xor_sync(0xffffffffu, ls2, 2);
        l1 = l1 * sc1 + ls1;  l2 = l2 * sc2 + ls2;
        m1 = mn1;             m2 = mn2;
#pragma unroll
        for (int t = 0; t < 16; t++) {
            ctx[t][0] *= sc1; ctx[t][1] *= sc1;
            ctx[t][2] *= sc2; ctx[t][3] *= sc2;
        }

        // ---- ctx += P V (4 k16 steps over the 64 kv rows)
#pragma unroll
        for (int ks2 = 0; ks2 < 4; ks2++) {
            uint32_t pah[4];
            pah[0] = pack_f16(sacc[2 * ks2][0],     sacc[2 * ks2][1]);
            pah[1] = pack_f16(sacc[2 * ks2][2],     sacc[2 * ks2][3]);
            pah[2] = pack_f16(sacc[2 * ks2 + 1][0], sacc[2 * ks2 + 1][1]);
            pah[3] = pack_f16(sacc[2 * ks2 + 1][2], sacc[2 * ks2 + 1][3]);
#pragma unroll
            for (int p2 = 0; p2 < 8; p2++) {
                uint32_t vbh[4];
                const uint32_t vo =
                    (uint32_t)((ks2 * 16 + vRow) * ROWB + (p2 * 16 + vSel * 8) * 2);
                ldsm_x4_t(vbh, stb + 1 * ATILE + vo);
                mma_f16(ctx[2 * p2],     pah, vbh);
                mma_f16(ctx[2 * p2 + 1], pah, vbh + 2);
            }
        }
    }

    // ---- epilogue: normalize, fp16 ctx
    const float inv1 = 1.0f / l1, inv2 = 1.0f / l2;
    const size_t o1 = (size_t)(b * cS + row1) * cH + nh * cHD;
    const size_t o2 = (size_t)(b * cS + row2) * cH + nh * cHD;
#pragma unroll
    for (int t = 0; t < 16; t++) {
        const int d = t * 8 + tig * 2;
        *(uint32_t*)&g_ctx_hi[o1 + d] = pack_f16(ctx[t][0] * inv1, ctx[t][1] * inv1);
        *(uint32_t*)&g_ctx_hi[o2 + d] = pack_f16(ctx[t][2] * inv2, ctx[t][3] * inv2);
    }
}

// ---------------------------------------------------------------------------
// Launch
// ---------------------------------------------------------------------------
extern "C" void kernel_launch(void* const* d_in, const int* in_sizes, int n_in,
                              void* d_out, int out_size)
{
    (void)in_sizes; (void)n_in; (void)out_size;
    const float* hidden   = (const float*)d_in[0];
    const float* residual = (const float*)d_in[1];
    const float* alibi    = (const float*)d_in[2];
    const float* W_qkv    = (const float*)d_in[4];
    const float* b_qkv    = (const float*)d_in[5];
    const float* W_dense  = (const float*)d_in[6];
    const float* b_dense  = (const float*)d_in[7];
    float* out = (float*)d_out;

    cudaFuncSetAttribute(tc_gemm_1t<0>, cudaFuncAttributeMaxDynamicSharedMemorySize, SMEM_1T);
    cudaFuncSetAttribute(tc_gemm_1t<1>, cudaFuncAttributeMaxDynamicSharedMemorySize, SMEM_1T);
    cudaFuncSetAttribute(attn_mma,      cudaFuncAttributeMaxDynamicSharedMemorySize, ATTN_SMEM);

    __half *hid_hi, *wq_hi, *wd_hi, *cx_hi;
    cudaGetSymbolAddress((void**)&hid_hi, g_hid_hi);
    cudaGetSymbolAddress((void**)&wq_hi,  g_wqkv_hi);
    cudaGetSymbolAddress((void**)&wd_hi,  g_wd_hi);
    cudaGetSymbolAddress((void**)&cx_hi,  g_ctx_hi);

    // 0) fp32 -> fp16
    split_fp32_hi<<<(cM * cH) / 1024, 256>>>((const float4*)hidden, (__half2*)hid_hi);
    split_fp32_hi<<<(cQKVN * cH) / 1024, 256>>>((const float4*)W_qkv, (__half2*)wq_hi);
    split_fp32_hi<<<(cH * cH) / 1024, 256>>>((const float4*)W_dense, (__half2*)wd_hi);

    // 1) QKV (1-term GEMM, supertile-swizzled 1-D grid) -> q/k/v fp16
    tc_gemm_1t<0><<<(cQKVN / 128) * MTILES, 256, SMEM_1T>>>(
        hid_hi, wq_hi, b_qkv, nullptr, nullptr);

    // 2) attention -> ctx fp16
    attn_mma<<<dim3(cS / ABQ, cB * cNH), 128, ATTN_SMEM>>>(alibi);

    // 3) dense (1-term, swizzled) + bias + residual -> out
    tc_gemm_1t<1><<<(cH / 128) * MTILES, 256, SMEM_1T>>>(
        cx_hi, wd_hi, b_dense, residual, out);
}

// round 17
// speedup vs baseline: 1.3552x; 1.3552x over previous
#include <cuda_runtime.h>
#include <cuda_fp16.h>
#include <math.h>
#include <cstdint>

// ---------------------------------------------------------------------------
// Problem constants
// ---------------------------------------------------------------------------
namespace {
constexpr int cB  = 2;
constexpr int cS  = 2048;
constexpr int cH  = 4096;
constexpr int cNH = 32;
constexpr int cHD = 128;
constexpr int cM  = cB * cS;      // 4096
constexpr int cQKVN = 3 * cH;     // 12288

// GEMM tiling (R14-proven): 128x128 tile, K-chunk 32, 3-stage cp.async ring
constexpr int GBM = 128, GBK = 32;
constexpr int SKB   = 80;                 // smem row stride bytes
constexpr int TILEB = GBM * SKB;          // 10240
constexpr int STAGE2 = 2 * TILEB;         // Ah,Bh
constexpr int SMEM_1T = 3 * STAGE2;       // 61440 (3-stage ring)
constexpr int MTILES = cM / GBM;          // 32
constexpr int GROUPM = 8;                 // supertile height (M-tiles)

// Attention (R14-proven): q-tile 64 rows, k-tile 32 rows, double-buffered
constexpr int ABQ = 64;
constexpr int ROWB = 272;                 // 128 fp16 + pad = 272 bytes
constexpr int ATILE = 32 * ROWB;          // 8704
constexpr int ASTAGE = 2 * ATILE;         // KH,VH = 17408
constexpr int AOFF_ALI = 2 * ASTAGE;      // 34816
constexpr int ATTN_SMEM = AOFF_ALI + 256; // 35072
}

// ---------------------------------------------------------------------------
// Scratch (__device__ globals)
// ---------------------------------------------------------------------------
__device__ __half g_qh[(size_t)cB * cNH * cS * cHD];
__device__ __half g_kh[(size_t)cB * cNH * cS * cHD];
__device__ __half g_vh[(size_t)cB * cNH * cS * cHD];

__device__ __half g_hid_hi[(size_t)cM * cH];
__device__ __half g_wqkv_hi[(size_t)cQKVN * cH];
__device__ __half g_wd_hi[(size_t)cH * cH];
__device__ __half g_ctx_hi[(size_t)cM * cH];

// ---------------------------------------------------------------------------
// PTX helpers — non-arch-specific only (mma.sync / ldmatrix / cp.async)
// ---------------------------------------------------------------------------
__device__ __forceinline__ uint32_t smem_u32(const void* p) {
    uint32_t a;
    asm("{ .reg .u64 t; cvta.to.shared.u64 t, %1; cvt.u32.u64 %0, t; }" : "=r"(a) : "l"(p));
    return a;
}
__device__ __forceinline__ void mma_f16(float* c, const uint32_t* a, const uint32_t* b) {
    asm volatile(
        "mma.sync.aligned.m16n8k16.row.col.f32.f16.f16.f32 "
        "{%0,%1,%2,%3}, {%4,%5,%6,%7}, {%8,%9}, {%0,%1,%2,%3};"
        : "+f"(c[0]), "+f"(c[1]), "+f"(c[2]), "+f"(c[3])
        : "r"(a[0]), "r"(a[1]), "r"(a[2]), "r"(a[3]), "r"(b[0]), "r"(b[1]));
}
__device__ __forceinline__ void ldsm_x4(uint32_t* r, uint32_t addr) {
    asm volatile("ldmatrix.sync.aligned.m8n8.x4.shared.b16 {%0,%1,%2,%3}, [%4];"
                 : "=r"(r[0]), "=r"(r[1]), "=r"(r[2]), "=r"(r[3]) : "r"(addr));
}
__device__ __forceinline__ void ldsm_x4_t(uint32_t* r, uint32_t addr) {
    asm volatile("ldmatrix.sync.aligned.m8n8.x4.trans.shared.b16 {%0,%1,%2,%3}, [%4];"
                 : "=r"(r[0]), "=r"(r[1]), "=r"(r[2]), "=r"(r[3]) : "r"(addr));
}
__device__ __forceinline__ void cp_async16(uint32_t s, const void* g) {
    asm volatile("cp.async.cg.shared.global [%0], [%1], 16;" :: "r"(s), "l"(g));
}
#define CP_COMMIT() asm volatile("cp.async.commit_group;" ::: "memory")
#define CP_WAIT(n)  asm volatile("cp.async.wait_group %0;" :: "n"(n) : "memory")

__device__ __forceinline__ uint32_t pack_f16(float lo, float hi) {
    uint32_t r;
    asm("cvt.rn.f16x2.f32 %0, %1, %2;" : "=r"(r) : "f"(hi), "f"(lo));
    return r;
}
// exp on the FMA pipe: valid for x <= 0; flushes below -87.
__device__ __forceinline__ float fast_exp(float x) {
    x = fmaxf(x, -87.0f);
    const float L2E = 1.4426950408889634f;
    float t = fmaf(x, L2E, 12582912.0f);
    float i = t - 12582912.0f;
    float f = fmaf(x, L2E, -i);
    float p =        1.3394582e-3f;
    p = fmaf(p, f, 9.6180217e-3f);
    p = fmaf(p, f, 5.5503368e-2f);
    p = fmaf(p, f, 2.4022652e-1f);
    p = fmaf(p, f, 6.9314718e-1f);
    p = fmaf(p, f, 1.0f);
    int e = (int)i;
    return __int_as_float((uint32_t)(e + 127) << 23) * p;
}

// ---------------------------------------------------------------------------
// fp32 -> fp16 (hi only)
// ---------------------------------------------------------------------------
__global__ __launch_bounds__(256) void split_fp32_hi(
    const float4* __restrict__ src, __half2* __restrict__ hi)
{
    const size_t i = (size_t)blockIdx.x * 256 + threadIdx.x;
    const float4 v = src[i];
    hi[2 * i]     = __halves2half2(__float2half_rn(v.x), __float2half_rn(v.y));
    hi[2 * i + 1] = __halves2half2(__float2half_rn(v.z), __float2half_rn(v.w));
}

// ---------------------------------------------------------------------------
// 1-term fp16 GEMM (R14 mainloop), L2 supertile swizzle on a 1-D grid.
// MODE 0: QKV -> scatter fp16 into g_qh/g_kh/g_vh (+bias); 3072 CTAs.
// MODE 1: dense -> out = acc + bias + residual (fp32); 1024 CTAs.
// ---------------------------------------------------------------------------
template <int MODE>
__global__ __launch_bounds__(256, 2) void tc_gemm_1t(
    const __half* __restrict__ Ahi, const __half* __restrict__ Bhi,
    const float* __restrict__ bias,
    const float* __restrict__ residual,
    float* __restrict__ out)
{
    extern __shared__ char smem[];
    const uint32_t sbase = smem_u32(smem);
    const int tid  = threadIdx.x;
    const int wid  = tid >> 5;
    const int lane = tid & 31;
    const int wm   = wid >> 2;
    const int wn   = wid & 3;

    // supertile swizzle: groups of GROUPM m-tiles; nx sweeps within a group
    constexpr int NXT = (MODE == 0) ? (cQKVN / 128) : (cH / 128);   // 96 / 32
    const int bid = blockIdx.x;
    const int grp = bid / (GROUPM * NXT);
    const int rem = bid % (GROUPM * NXT);
    const int my  = grp * GROUPM + (rem % GROUPM);
    const int nx  = rem / GROUPM;
    const int bm  = my * GBM;
    const int obase = nx * 128;

    const __half* Ah = Ahi + (size_t)bm * cH;
    const __half* Bh = Bhi + (size_t)obase * cH;

    float acc[4][4][4];
#pragma unroll
    for (int mi = 0; mi < 4; mi++)
#pragma unroll
        for (int nj = 0; nj < 4; nj++)
#pragma unroll
            for (int r = 0; r < 4; r++) acc[mi][nj][r] = 0.f;

    const int aRow = ((lane >> 3) & 1) * 8 + (lane & 7);
    const int aK   = (lane >> 4) * 8;
    const int bRow = ((lane >> 4) << 3) + (lane & 7);   // n-row within 16
    const int bK   = ((lane >> 3) & 1) * 8;

    auto load_chunk = [&](int stage, int k0) {
        const uint32_t sg = sbase + stage * STAGE2;
#pragma unroll
        for (int it = 0; it < 2; ++it) {
            const int c   = tid + it * 256;
            const int row = c >> 2;
            const int kc  = c & 3;
            const uint32_t so = (uint32_t)(row * SKB + kc * 16);
            const size_t  go  = (size_t)row * cH + k0 + kc * 8;
            cp_async16(sg + 0 * TILEB + so, Ah + go);
            cp_async16(sg + 1 * TILEB + so, Bh + go);
        }
    };

    constexpr int NCH = cH / GBK;   // 128
    load_chunk(0, 0);
    CP_COMMIT();
    load_chunk(1, GBK);
    CP_COMMIT();

    int cstage = 0;
    for (int ch = 0; ch < NCH; ++ch) {
        if (ch + 1 < NCH) { CP_WAIT(1); } else { CP_WAIT(0); }
        __syncthreads();
        if (ch + 2 < NCH) {
            int lstage = cstage - 1; if (lstage < 0) lstage = 2;   // (cstage+2)%3
            load_chunk(lstage, (ch + 2) * GBK);
            CP_COMMIT();
        }
        const uint32_t st = sbase + cstage * STAGE2;
#pragma unroll
        for (int ks = 0; ks < 2; ++ks) {
            uint32_t ah[4][4];
#pragma unroll
            for (int mi = 0; mi < 4; ++mi) {
                const uint32_t ao =
                    (uint32_t)((wm * 64 + mi * 16 + aRow) * SKB + (ks * 16 + aK) * 2);
                ldsm_x4(ah[mi], st + ao);
            }
#pragma unroll
            for (int nj2 = 0; nj2 < 2; ++nj2) {
                uint32_t bb[4];
                const uint32_t bo =
                    (uint32_t)((wn * 32 + nj2 * 16 + bRow) * SKB + (ks * 16 + bK) * 2);
                ldsm_x4(bb, st + TILEB + bo);
#pragma unroll
                for (int mi = 0; mi < 4; ++mi) {
                    mma_f16(acc[mi][2 * nj2],     ah[mi], bb);
                    mma_f16(acc[mi][2 * nj2 + 1], ah[mi], bb + 2);
                }
            }
        }
        cstage = (cstage == 2) ? 0 : cstage + 1;
    }

    const int l4 = lane >> 2;
    const int l2 = (lane & 3) * 2;
#pragma unroll
    for (int mi = 0; mi < 4; ++mi) {
#pragma unroll
        for (int nj = 0; nj < 4; ++nj) {
            const int colT = wn * 32 + nj * 8 + l2;
            const int o    = obase + colT;
            const float2 bia = *(const float2*)&bias[o];
#pragma unroll
            for (int half = 0; half < 2; ++half) {
                const int m = bm + wm * 64 + mi * 16 + l4 + half * 8;
                const float vx = acc[mi][nj][half * 2 + 0] + bia.x;
                const float vy = acc[mi][nj][half * 2 + 1] + bia.y;
                if (MODE == 0) {
                    const int nh = nx / 3;
                    const int t  = nx % 3;
                    __half* dst = (t == 0) ? g_qh : (t == 1) ? g_kh : g_vh;
                    const int b = m / cS, s = m % cS;
                    const size_t idx =
                        ((size_t)(b * cNH + nh) * cS + s) * cHD + colT;
                    *(uint32_t*)&dst[idx] = pack_f16(vx, vy);
                } else {
                    const size_t idx = (size_t)m * cH + o;
                    const float2 res = *(const float2*)&residual[idx];
                    float2 v; v.x = vx + res.x; v.y = vy + res.y;
                    *(float2*)&out[idx] = v;
                }
            }
        }
    }
}

// ---------------------------------------------------------------------------
// Attention (R14-proven): 64 q-rows/CTA, 4 warps; 32-row K/V tiles
// double-buffered. QK and PV both 1-term fp16.
// ---------------------------------------------------------------------------
__global__ __launch_bounds__(128) void attn_mma(const float* __restrict__ alibi)
{
    extern __shared__ char sm[];
    const uint32_t sb = smem_u32(sm);
    const int tid  = threadIdx.x;
    const int lane = tid & 31;
    const int w    = tid >> 5;
    const int qi   = (cS / ABQ - 1) - blockIdx.x;   // big tiles first
    const int bh   = blockIdx.y;
    const int b    = bh >> 5;
    const int nh   = bh & 31;
    const size_t hb = (size_t)bh * cS * cHD;
    const float inv_norm = 0.08838834764831845f;

    const int g    = lane >> 2;
    const int tig  = lane & 3;
    const int aRow = ((lane >> 3) & 1) * 8 + (lane & 7);
    const int aK   = (lane >> 4) * 8;
    const int bRow = ((lane >> 4) << 3) + (lane & 7);   // n-row within 16
    const int bK   = ((lane >> 3) & 1) * 8;
    const int vRow = (lane & 7) + (((lane >> 3) & 1) << 3);
    const int vSel = lane >> 4;

    // ---- stage Q (64 rows) across both stage areas (pre-loop)
#pragma unroll
    for (int i = 0; i < 8; i++) {
        const int id = tid + i * 128;
        const int r = id >> 4, c = id & 15;
        const size_t go = hb + (size_t)(qi * ABQ + r) * cHD + c * 8;
        cp_async16(sb + (uint32_t)(r * ROWB + c * 16), g_qh + go);
    }
    CP_COMMIT(); CP_WAIT(0);
    __syncthreads();

    uint32_t qh[8][4];
#pragma unroll
    for (int ks = 0; ks < 8; ks++) {
        const uint32_t ao = (uint32_t)((w * 16 + aRow) * ROWB + (ks * 16 + aK) * 2);
        ldsm_x4(qh[ks], sb + ao);
    }
    __syncthreads();

    float ctx[16][4];
#pragma unroll
    for (int t = 0; t < 16; t++)
#pragma unroll
        for (int r = 0; r < 4; r++) ctx[t][r] = 0.f;
    float m1 = -INFINITY, m2 = -INFINITY, l1 = 0.f, l2 = 0.f;
    const int row1 = qi * ABQ + w * 16 + g;
    const int row2 = row1 + 8;

    auto load_kv = [&](int stage, int kt) {
        const uint32_t stb = sb + stage * ASTAGE;
#pragma unroll
        for (int i = 0; i < 4; i++) {
            const int id = tid + i * 128;
            const int r = id >> 4, c = id & 15;
            const size_t go = hb + (size_t)(kt * 32 + r) * cHD + c * 8;
            const uint32_t so = (uint32_t)(r * ROWB + c * 16);
            cp_async16(stb + 0 * ATILE + so, g_kh + go);
            cp_async16(stb + 1 * ATILE + so, g_vh + go);
        }
        if (tid < 32)
            ((float*)(sm + AOFF_ALI + stage * 128))[tid] =
                alibi[(size_t)bh * cS + kt * 32 + tid];
    };

    const int nkt = 2 * (qi + 1);
    load_kv(0, 0);
    CP_COMMIT();

    for (int kt = 0; kt < nkt; kt++) {
        CP_WAIT(0);
        __syncthreads();
        if (kt + 1 < nkt) { load_kv((kt + 1) & 1, kt + 1); CP_COMMIT(); }
        const uint32_t stb = sb + (kt & 1) * ASTAGE;
        const float* als = (const float*)(sm + AOFF_ALI + (kt & 1) * 128);

        // ---- S = Q K^T (1-term)
        float sacc[4][4];
#pragma unroll
        for (int j = 0; j < 4; j++)
#pragma unroll
            for (int r = 0; r < 4; r++) sacc[j][r] = 0.f;

#pragma unroll
        for (int nj2 = 0; nj2 < 2; ++nj2) {
#pragma unroll
            for (int ks = 0; ks < 8; ks++) {
                uint32_t kb[4];
                const uint32_t bo =
                    (uint32_t)((nj2 * 16 + bRow) * ROWB + (ks * 16 + bK) * 2);
                ldsm_x4(kb, stb + bo);
                mma_f16(sacc[2 * nj2],     qh[ks], kb);
                mma_f16(sacc[2 * nj2 + 1], qh[ks], kb + 2);
            }
        }

        // ---- scale + alibi + causal mask (only last two tiles can mask)
        const bool maskt = (kt >= 2 * qi);
#pragma unroll
        for (int j = 0; j < 4; j++) {
            const int c0 = j * 8 + tig * 2;
            const float a0 = als[c0], a1 = als[c0 + 1];
            sacc[j][0] = fmaf(sacc[j][0], inv_norm, a0);
            sacc[j][1] = fmaf(sacc[j][1], inv_norm, a1);
            sacc[j][2] = fmaf(sacc[j][2], inv_norm, a0);
            sacc[j][3] = fmaf(sacc[j][3], inv_norm, a1);
            if (maskt) {
                const int cg = kt * 32 + c0;
                if (cg     > row1) sacc[j][0] = -100000.0f;
                if (cg + 1 > row1) sacc[j][1] = -100000.0f;
                if (cg     > row2) sacc[j][2] = -100000.0f;
                if (cg + 1 > row2) sacc[j][3] = -100000.0f;
            }
        }

        // ---- online softmax
        float mx1 = -INFINITY, mx2 = -INFINITY;
#pragma unroll
        for (int j = 0; j < 4; j++) {
            mx1 = fmaxf(mx1, fmaxf(sacc[j][0], sacc[j][1]));
            mx2 = fmaxf(mx2, fmaxf(sacc[j][2], sacc[j][3]));
        }
        mx1 = fmaxf(mx1, __shfl_xor_sync(0xffffffffu, mx1, 1));
        mx1 = fmaxf(mx1, __shfl_xor_sync(0xffffffffu, mx1, 2));
        mx2 = fmaxf(mx2, __shfl_xor_sync(0xffffffffu, mx2, 1));
        mx2 = fmaxf(mx2, __shfl_xor_sync(0xffffffffu, mx2, 2));

        const float mn1 = fmaxf(m1, mx1), mn2 = fmaxf(m2, mx2);
        const float sc1 = fast_exp(m1 - mn1), sc2 = fast_exp(m2 - mn2);
        float ls1 = 0.f, ls2 = 0.f;
#pragma unroll
        for (int j = 0; j < 4; j++) {
            sacc[j][0] = fast_exp(sacc[j][0] - mn1);
            sacc[j][1] = fast_exp(sacc[j][1] - mn1);
            sacc[j][2] = fast_exp(sacc[j][2] - mn2);
            sacc[j][3] = fast_exp(sacc[j][3] - mn2);
            ls1 += sacc[j][0] + sacc[j][1];
            ls2 += sacc[j][2] + sacc[j][3];
        }
        ls1 += __shfl_xor_sync(0xffffffffu, ls1, 1);
        ls1 += __shfl_xor_sync(0xffffffffu, ls1, 2);
        ls2 += __shfl_xor_sync(0xffffffffu, ls2, 1);
        ls2 += __shfl_xor_sync(0xffffffffu, ls2, 2);
        l1 = l1 * sc1 + ls1;  l2 = l2 * sc2 + ls2;
        m1 = mn1;             m2 = mn2;
#pragma unroll
        for (int t = 0; t < 16; t++) {
            ctx[t][0] *= sc1; ctx[t][1] *= sc1;
            ctx[t][2] *= sc2; ctx[t][3] *= sc2;
        }

        // ---- ctx += P V (1-term)
#pragma unroll
        for (int ks2 = 0; ks2 < 2; ks2++) {
            uint32_t pah[4];
            pah[0] = pack_f16(sacc[2 * ks2][0],     sacc[2 * ks2][1]);
            pah[1] = pack_f16(sacc[2 * ks2][2],     sacc[2 * ks2][3]);
            pah[2] = pack_f16(sacc[2 * ks2 + 1][0], sacc[2 * ks2 + 1][1]);
            pah[3] = pack_f16(sacc[2 * ks2 + 1][2], sacc[2 * ks2 + 1][3]);
#pragma unroll
            for (int p2 = 0; p2 < 8; p2++) {
                uint32_t vbh[4];
                const uint32_t vo =
                    (uint32_t)((ks2 * 16 + vRow) * ROWB + (p2 * 16 + vSel * 8) * 2);
                ldsm_x4_t(vbh, stb + 1 * ATILE + vo);
                mma_f16(ctx[2 * p2],     pah, vbh);
                mma_f16(ctx[2 * p2 + 1], pah, vbh + 2);
            }
        }
    }

    // ---- epilogue: normalize, fp16 ctx
    const float inv1 = 1.0f / l1, inv2 = 1.0f / l2;
    const size_t o1 = (size_t)(b * cS + row1) * cH + nh * cHD;
    const size_t o2 = (size_t)(b * cS + row2) * cH + nh * cHD;
#pragma unroll
    for (int t = 0; t < 16; t++) {
        const int d = t * 8 + tig * 2;
        *(uint32_t*)&g_ctx_hi[o1 + d] = pack_f16(ctx[t][0] * inv1, ctx[t][1] * inv1);
        *(uint32_t*)&g_ctx_hi[o2 + d] = pack_f16(ctx[t][2] * inv2, ctx[t][3] * inv2);
    }
}

// ---------------------------------------------------------------------------
// Launch
// ---------------------------------------------------------------------------
extern "C" void kernel_launch(void* const* d_in, const int* in_sizes, int n_in,
                              void* d_out, int out_size)
{
    (void)in_sizes; (void)n_in; (void)out_size;
    const float* hidden   = (const float*)d_in[0];
    const float* residual = (const float*)d_in[1];
    const float* alibi    = (const float*)d_in[2];
    const float* W_qkv    = (const float*)d_in[4];
    const float* b_qkv    = (const float*)d_in[5];
    const float* W_dense  = (const float*)d_in[6];
    const float* b_dense  = (const float*)d_in[7];
    float* out = (float*)d_out;

    cudaFuncSetAttribute(tc_gemm_1t<0>, cudaFuncAttributeMaxDynamicSharedMemorySize, SMEM_1T);
    cudaFuncSetAttribute(tc_gemm_1t<1>, cudaFuncAttributeMaxDynamicSharedMemorySize, SMEM_1T);
    cudaFuncSetAttribute(attn_mma,      cudaFuncAttributeMaxDynamicSharedMemorySize, ATTN_SMEM);

    __half *hid_hi, *wq_hi, *wd_hi, *cx_hi;
    cudaGetSymbolAddress((void**)&hid_hi, g_hid_hi);
    cudaGetSymbolAddress((void**)&wq_hi,  g_wqkv_hi);
    cudaGetSymbolAddress((void**)&wd_hi,  g_wd_hi);
    cudaGetSymbolAddress((void**)&cx_hi,  g_ctx_hi);

    // 0) fp32 -> fp16 (hi only, everywhere)
    split_fp32_hi<<<(cM * cH) / 1024, 256>>>((const float4*)hidden, (__half2*)hid_hi);
    split_fp32_hi<<<(cQKVN * cH) / 1024, 256>>>((const float4*)W_qkv, (__half2*)wq_hi);
    split_fp32_hi<<<(cH * cH) / 1024, 256>>>((const float4*)W_dense, (__half2*)wd_hi);

    // 1) QKV (1-term GEMM, supertile-swizzled 1-D grid) -> q/k/v fp16
    tc_gemm_1t<0><<<(cQKVN / 128) * MTILES, 256, SMEM_1T>>>(
        hid_hi, wq_hi, b_qkv, nullptr, nullptr);

    // 2) attention -> ctx fp16
    attn_mma<<<dim3(cS / ABQ, cB * cNH), 128, ATTN_SMEM>>>(alibi);

    // 3) dense (1-term, swizzled) + bias + residual -> out
    tc_gemm_1t<1><<<(cH / 128) * MTILES, 256, SMEM_1T>>>(
        cx_hi, wd_hi, b_dense, residual, out);
}